// round 1
// baseline (speedup 1.0000x reference)
#include <cuda_runtime.h>
#include <cuda_bf16.h>
#include <stdint.h>

// Problem constants (fixed by the dataset): bs=16, nq=900, nc=91, T=1600
#define NQTOT 14400      // bs*nq
#define NCLS  91
#define TTOT  1600

#define TILE_N 32
#define TILE_T 64
#define NTH    128
#define CLS_PITCH 92     // padded shared pitch

// Scratch: per-(prediction,class) focal cost table, scaled by COST_CLASS=2.
__device__ float g_cls_tab[NQTOT * NCLS];   // 5.24 MB, fits in L2

// ---------------------------------------------------------------------------
// Kernel A: class-cost table.  tab[n,c] = 2 * (pos(n,c) - neg(n,c))
// ---------------------------------------------------------------------------
__global__ void cls_table_kernel(const float* __restrict__ logits,
                                 float* __restrict__ tab)
{
    int i = blockIdx.x * blockDim.x + threadIdx.x;
    if (i >= NQTOT * NCLS) return;
    float x = logits[i];
    float p = __fdividef(1.0f, 1.0f + __expf(-x));
    float omp = 1.0f - p;
    float pos = 0.25f * omp * omp * (-__logf(p + 1e-8f));
    float neg = 0.75f * p * p * (-__logf(omp + 1e-8f));
    tab[i] = 2.0f * (pos - neg);
}

// ---------------------------------------------------------------------------
// Kernel B: pairwise cost.  Block = 32 preds x 64 targets, thread = 4x4.
// C[n,t] = 5*L1(nc,tc) + tab[n, id[t]] - 2*GIoU(nx, tx)
// ---------------------------------------------------------------------------
__global__ __launch_bounds__(NTH)
void pair_cost_kernel(const float*  __restrict__ pboxes,   // [NQTOT,4] cxcywh
                      const float*  __restrict__ tboxes,   // [TTOT,4] cxcywh
                      const int*    __restrict__ tids,     // [TTOT]
                      const float*  __restrict__ tab,      // [NQTOT,NCLS]
                      float*        __restrict__ out)      // [NQTOT,TTOT]
{
    __shared__ float  s_cls[TILE_N * CLS_PITCH];
    __shared__ float4 s_tc[TILE_T];   // target cxcywh
    __shared__ float4 s_tx[TILE_T];   // target xyxy
    __shared__ float  s_ta[TILE_T];   // target area
    __shared__ int    s_id[TILE_T];   // target class id

    const int tb = blockIdx.x;            // 0..24
    const int nb = blockIdx.y;            // 0..449
    const int n0 = nb * TILE_N;
    const int t0 = tb * TILE_T;
    const int tid = threadIdx.x;

    // --- stage class-cost tile (32 rows x 91 cols, pitch 92) ---
    #pragma unroll
    for (int idx = tid; idx < TILE_N * CLS_PITCH; idx += NTH) {
        int r = idx / CLS_PITCH;
        int c = idx - r * CLS_PITCH;
        s_cls[idx] = (c < NCLS) ? tab[(n0 + r) * NCLS + c] : 0.0f;
    }
    // --- stage target tile ---
    if (tid < TILE_T) {
        int t = t0 + tid;
        float4 b = reinterpret_cast<const float4*>(tboxes)[t];
        s_tc[tid] = b;
        float hw = 0.5f * b.z, hh = 0.5f * b.w;
        s_tx[tid] = make_float4(b.x - hw, b.y - hh, b.x + hw, b.y + hh);
        s_ta[tid] = b.z * b.w;
        s_id[tid] = tids[t];
    }
    __syncthreads();

    const int txg   = tid & 15;    // 16 target groups of 4
    const int nyg   = tid >> 4;    // 8 pred groups of 4
    const int nbase = nyg * 4;

    // --- per-thread prediction data (4 rows) in registers ---
    float4 ncv[4], nxv[4];
    float  nav[4];
    #pragma unroll
    for (int i = 0; i < 4; i++) {
        float4 b = reinterpret_cast<const float4*>(pboxes)[n0 + nbase + i];
        ncv[i] = b;
        float hw = 0.5f * b.z, hh = 0.5f * b.w;
        nxv[i] = make_float4(b.x - hw, b.y - hh, b.x + hw, b.y + hh);
        nav[i] = b.z * b.w;
    }

    float res[16];
    #pragma unroll
    for (int j = 0; j < 4; j++) {
        const int lt = txg * 4 + j;
        const float4 tc = s_tc[lt];
        const float4 tx = s_tx[lt];
        const float  ta = s_ta[lt];
        const int    id = s_id[lt];
        #pragma unroll
        for (int i = 0; i < 4; i++) {
            const float cls = s_cls[(nbase + i) * CLS_PITCH + id];
            const float4 nc = ncv[i];
            const float4 nx = nxv[i];
            // L1 over cxcywh
            float l1 = fabsf(nc.x - tc.x) + fabsf(nc.y - tc.y)
                     + fabsf(nc.z - tc.z) + fabsf(nc.w - tc.w);
            // intersection
            float ltx = fmaxf(nx.x, tx.x), lty = fmaxf(nx.y, tx.y);
            float rbx = fminf(nx.z, tx.z), rby = fminf(nx.w, tx.w);
            float wi = fmaxf(rbx - ltx, 0.0f);
            float hi = fmaxf(rby - lty, 0.0f);
            float inter = wi * hi;
            float uni = nav[i] + ta - inter;
            // enclosing box (always non-degenerate: max-min >= 0)
            float ex0 = fminf(nx.x, tx.x), ey0 = fminf(nx.y, tx.y);
            float ex1 = fmaxf(nx.z, tx.z), ey1 = fmaxf(nx.w, tx.w);
            float ae = (ex1 - ex0) * (ey1 - ey0);
            float giou = __fdividef(inter, uni) - __fdividef(ae - uni, ae);
            res[i * 4 + j] = 5.0f * l1 + cls - 2.0f * giou;
        }
    }

    // --- vectorized stores: 4 consecutive targets per row ---
    const int tcol = t0 + txg * 4;
    #pragma unroll
    for (int i = 0; i < 4; i++) {
        size_t n = (size_t)(n0 + nbase + i);
        float4 v = make_float4(res[i*4+0], res[i*4+1], res[i*4+2], res[i*4+3]);
        reinterpret_cast<float4*>(out)[(n * TTOT + tcol) >> 2] = v;
    }
}

// ---------------------------------------------------------------------------
extern "C" void kernel_launch(void* const* d_in, const int* in_sizes, int n_in,
                              void* d_out, int out_size)
{
    const float* pred_logits = (const float*)d_in[0];  // [16,900,91]
    const float* pred_boxes  = (const float*)d_in[1];  // [16,900,4]
    const int*   tgt_ids     = (const int*)  d_in[2];  // [1600]
    const float* tgt_bbox    = (const float*)d_in[3];  // [1600,4]
    float*       out         = (float*)d_out;          // [16,900,1600]

    float* tab = nullptr;
    cudaGetSymbolAddress((void**)&tab, g_cls_tab);

    const int totalA = NQTOT * NCLS;
    cls_table_kernel<<<(totalA + 255) / 256, 256>>>(pred_logits, tab);

    dim3 grid(TTOT / TILE_T, NQTOT / TILE_N);  // (25, 450)
    pair_cost_kernel<<<grid, NTH>>>(pred_boxes, tgt_bbox, tgt_ids, tab, out);
}